// round 14
// baseline (speedup 1.0000x reference)
#include <cuda_runtime.h>
#include <cstdint>

#define INV_CAP (1 << 20)
#define MAX_K   12288   // smem staging limit: 48KB

// All entries of g_inv[0..N) and g_next[0..K) are rewritten on every call by
// build_all_kernel (deterministic, no atomics), so no init/staleness issues.
__device__ int g_inv[INV_CAP];   // last j with idx[j]==col, else -1
__device__ int g_next[MAX_K];    // nearest earlier duplicate of j, else -1
__device__ int g_dup;            // cleared+set by block 0 each call

__device__ __forceinline__ bool detect_is64(const unsigned int* w, int K) {
    // int64 small non-negative indices => all odd 32-bit words are zero.
    if (K >= 8) return ((w[1] | w[3] | w[5] | w[7]) == 0u);
    if (K >= 2) return (w[1] == 0u);
    return false;
}

__device__ __forceinline__ int load_idx(const void* idx_raw, int j, bool is64) {
    return is64 ? (int)((const long long*)idx_raw)[j]
                : ((const int*)idx_raw)[j];
}

// One launch, grid covers all N columns. Each block stages idx in smem; each
// thread scans K entries for its column (smem broadcast reads). Block 0 also
// builds duplicate chains and the dup flag. Fully deterministic.
__global__ void build_all_kernel(const void* __restrict__ idx_raw, int K, int N) {
    extern __shared__ int s_col[];
    bool is64 = detect_is64((const unsigned int*)idx_raw, K);
    for (int t = threadIdx.x; t < K; t += blockDim.x)
        s_col[t] = load_idx(idx_raw, t, is64);
    if (blockIdx.x == 0 && threadIdx.x == 0) g_dup = 0;
    __syncthreads();

    int col = blockIdx.x * blockDim.x + threadIdx.x;
    if (col < N) {
        int last = -1;
        for (int t = 0; t < K; t++)
            if (s_col[t] == col) last = t;
        g_inv[col] = last;
    }

    if (blockIdx.x == 0) {
        for (int j = threadIdx.x; j < K; j += blockDim.x) {
            int c = s_col[j];
            int pred = -1;
            for (int t = 0; t < j; t++)
                if (s_col[t] == c) pred = t;   // ends at nearest earlier
            g_next[j] = pred;
            if (pred >= 0) g_dup = 1;          // all writers store 1
        }
    }
}

__device__ __forceinline__ float chain_sum(const float* __restrict__ rb, int j) {
    float v = 0.f;
    while (j >= 0) { v += __ldg(rb + j); j = g_next[j]; }
    return v;
}

__device__ __forceinline__ float4 gather4(const float* __restrict__ rb,
                                          const int4 iv, bool dup) {
    float4 v;
    if (!dup) {
        v.x = (iv.x >= 0) ? __ldg(rb + iv.x) : 0.f;
        v.y = (iv.y >= 0) ? __ldg(rb + iv.y) : 0.f;
        v.z = (iv.z >= 0) ? __ldg(rb + iv.z) : 0.f;
        v.w = (iv.w >= 0) ? __ldg(rb + iv.w) : 0.f;
    } else {
        v.x = (iv.x >= 0) ? chain_sum(rb, iv.x) : 0.f;
        v.y = (iv.y >= 0) ? chain_sum(rb, iv.y) : 0.f;
        v.z = (iv.z >= 0) ? chain_sum(rb, iv.z) : 0.f;
        v.w = (iv.w >= 0) ? chain_sum(rb, iv.w) : 0.f;
    }
    return v;
}

// Hot loop: one thread = one 8-column group x 8 batch rows.
// Zero path: 2 x STG.128 per row, warp covers 1KB contiguous per row.
__global__ void __launch_bounds__(256)
fused_write_kernel(const float* __restrict__ in,
                   float* __restrict__ out,
                   int B, int N, int K, int rows_per_thread) {
    int n_groups = (N + 7) >> 3;
    int g = blockIdx.x * blockDim.x + threadIdx.x;
    if (g >= n_groups) return;
    int n0 = g * 8;

    int b0 = blockIdx.y * rows_per_thread;
    int bend = b0 + rows_per_thread;
    if (bend > B) bend = B;

    if (n0 + 8 <= N && (N & 3) == 0) {
        int4 iv0 = *reinterpret_cast<const int4*>(&g_inv[n0]);
        int4 iv1 = *reinterpret_cast<const int4*>(&g_inv[n0 + 4]);
        bool anyhit = (iv0.x >= 0) | (iv0.y >= 0) | (iv0.z >= 0) | (iv0.w >= 0) |
                      (iv1.x >= 0) | (iv1.y >= 0) | (iv1.z >= 0) | (iv1.w >= 0);
        float4 z = make_float4(0.f, 0.f, 0.f, 0.f);
        if (!anyhit) {
            #pragma unroll 4
            for (int b = b0; b < bend; b++) {
                float4* p = reinterpret_cast<float4*>(out + (long long)b * N + n0);
                __stcs(p, z);
                __stcs(p + 1, z);
            }
        } else {
            bool dup = (g_dup != 0);       // uniform; zero path never sees this
            for (int b = b0; b < bend; b++) {
                const float* rb = in + (long long)b * K;
                float4 v0 = gather4(rb, iv0, dup);
                float4 v1 = gather4(rb, iv1, dup);
                float4* p = reinterpret_cast<float4*>(out + (long long)b * N + n0);
                __stcs(p, v0);
                __stcs(p + 1, v1);
            }
        }
    } else {
        // Scalar tail / unaligned fallback (duplicate-exact via chain).
        for (int c = n0; c < n0 + 8 && c < N; c++) {
            int j = g_inv[c];
            for (int b = b0; b < bend; b++) {
                const float* rb = in + (long long)b * K;
                float v = (j >= 0) ? chain_sum(rb, j) : 0.f;
                out[(long long)b * N + c] = v;
            }
        }
    }
}

// ---- Fallback path (shape outside map limits): fill + atomic scatter ----
__global__ void zero_fill_kernel(float4* __restrict__ out4, long long n4) {
    long long i = (long long)blockIdx.x * blockDim.x + threadIdx.x;
    long long stride = (long long)gridDim.x * blockDim.x;
    float4 z = make_float4(0.f, 0.f, 0.f, 0.f);
    for (; i < n4; i += stride) out4[i] = z;
}

__global__ void scatter_add_kernel(const float* __restrict__ in,
                                   const void* __restrict__ idx_raw,
                                   float* __restrict__ out,
                                   int B, int K, long long N) {
    long long t = (long long)blockIdx.x * blockDim.x + threadIdx.x;
    long long total = (long long)B * K;
    if (t >= total) return;
    int b = (int)(t / K);
    int j = (int)(t % K);
    bool is64 = detect_is64((const unsigned int*)idx_raw, K);
    long long col = load_idx(idx_raw, j, is64);
    atomicAdd(&out[(long long)b * N + col], in[(long long)b * K + j]);
}

extern "C" void kernel_launch(void* const* d_in, const int* in_sizes, int n_in,
                              void* d_out, int out_size) {
    const float* inputs = (const float*)d_in[0];
    const void* idx = d_in[1];
    float* out = (float*)d_out;

    int total_in = in_sizes[0];   // B * K
    int K = in_sizes[1];          // observed count
    int B = total_in / K;
    long long Nll = (long long)out_size / B;
    int N = (int)Nll;

    if (Nll <= INV_CAP && K <= MAX_K) {
        // Node 1: deterministic all-column build (no init, no fixup needed).
        int bblocks = (N + 255) / 256;
        build_all_kernel<<<bblocks, 256, K * (int)sizeof(int)>>>(idx, K, N);

        // Node 2: single fused streaming write of the whole output.
        const int ROWS = 8;
        int n_groups = (N + 7) / 8;
        dim3 block(256, 1, 1);
        dim3 grid((n_groups + 255) / 256, (B + ROWS - 1) / ROWS, 1);
        fused_write_kernel<<<grid, block>>>(inputs, out, B, N, K, ROWS);
    } else {
        // Fallback: zero-fill + atomic scatter.
        long long n4 = (long long)out_size / 4;
        int threads = 256;
        long long blocks_ll = (n4 + threads - 1) / threads;
        int blocks = (blocks_ll > 0x7FFFFFF0LL) ? 0x7FFFFFF0 : (int)blocks_ll;
        zero_fill_kernel<<<blocks, threads>>>((float4*)out, n4);
        long long tail_start = n4 * 4;
        if (tail_start < (long long)out_size) {
            cudaMemsetAsync(out + tail_start, 0,
                            ((long long)out_size - tail_start) * sizeof(float), 0);
        }
        long long total = (long long)B * K;
        int sblocks = (int)((total + threads - 1) / threads);
        scatter_add_kernel<<<sblocks, threads>>>(inputs, idx, out, B, K, Nll);
    }
}

// round 16
// speedup vs baseline: 1.1041x; 1.1041x over previous
#include <cuda_runtime.h>
#include <cstdint>

#define INV_CAP (1 << 20)
#define MAX_K   12288   // smem staging limit: 48KB

// All entries of g_inv[0..N) and g_next[0..K) are rewritten on every call by
// build_all_kernel (deterministic, no atomics), so no init/staleness issues.
__device__ int g_inv[INV_CAP];   // last j with idx[j]==col, else -1
__device__ int g_next[MAX_K];    // nearest earlier duplicate of j, else -1
__device__ int g_dup;            // cleared+set by block 0 each call

__device__ __forceinline__ bool detect_is64(const unsigned int* w, int K) {
    // int64 small non-negative indices => all odd 32-bit words are zero.
    if (K >= 8) return ((w[1] | w[3] | w[5] | w[7]) == 0u);
    if (K >= 2) return (w[1] == 0u);
    return false;
}

__device__ __forceinline__ int load_idx(const void* idx_raw, int j, bool is64) {
    return is64 ? (int)((const long long*)idx_raw)[j]
                : ((const int*)idx_raw)[j];
}

// 256-bit streaming store (sm_100+). p must be 32B-aligned.
__device__ __forceinline__ void stcs256(float* p, float4 a, float4 b) {
    asm volatile(
        "st.global.cs.v8.f32 [%0], {%1,%2,%3,%4,%5,%6,%7,%8};"
        :: "l"(p),
           "f"(a.x), "f"(a.y), "f"(a.z), "f"(a.w),
           "f"(b.x), "f"(b.y), "f"(b.z), "f"(b.w)
        : "memory");
}

// One launch, grid covers all N columns. Each block stages idx in smem; each
// thread scans K entries for its column (smem broadcast reads). Block 0 also
// builds duplicate chains and the dup flag. Fully deterministic.
__global__ void build_all_kernel(const void* __restrict__ idx_raw, int K, int N) {
    extern __shared__ int s_col[];
    bool is64 = detect_is64((const unsigned int*)idx_raw, K);
    for (int t = threadIdx.x; t < K; t += blockDim.x)
        s_col[t] = load_idx(idx_raw, t, is64);
    if (blockIdx.x == 0 && threadIdx.x == 0) g_dup = 0;
    __syncthreads();

    int col = blockIdx.x * blockDim.x + threadIdx.x;
    if (col < N) {
        int last = -1;
        for (int t = 0; t < K; t++)
            if (s_col[t] == col) last = t;
        g_inv[col] = last;
    }

    if (blockIdx.x == 0) {
        for (int j = threadIdx.x; j < K; j += blockDim.x) {
            int c = s_col[j];
            int pred = -1;
            for (int t = 0; t < j; t++)
                if (s_col[t] == c) pred = t;   // ends at nearest earlier
            g_next[j] = pred;
            if (pred >= 0) g_dup = 1;          // all writers store 1
        }
    }
}

__device__ __forceinline__ float chain_sum(const float* __restrict__ rb, int j) {
    float v = 0.f;
    while (j >= 0) { v += __ldg(rb + j); j = g_next[j]; }
    return v;
}

__device__ __forceinline__ float4 gather4(const float* __restrict__ rb,
                                          const int4 iv, bool dup) {
    float4 v;
    if (!dup) {
        v.x = (iv.x >= 0) ? __ldg(rb + iv.x) : 0.f;
        v.y = (iv.y >= 0) ? __ldg(rb + iv.y) : 0.f;
        v.z = (iv.z >= 0) ? __ldg(rb + iv.z) : 0.f;
        v.w = (iv.w >= 0) ? __ldg(rb + iv.w) : 0.f;
    } else {
        v.x = (iv.x >= 0) ? chain_sum(rb, iv.x) : 0.f;
        v.y = (iv.y >= 0) ? chain_sum(rb, iv.y) : 0.f;
        v.z = (iv.z >= 0) ? chain_sum(rb, iv.z) : 0.f;
        v.w = (iv.w >= 0) ? chain_sum(rb, iv.w) : 0.f;
    }
    return v;
}

// Hot loop: one thread = one 8-column group x 8 batch rows.
// Zero path: 1 x STG.256 per row; warp covers 1KB contiguous per instruction.
__global__ void __launch_bounds__(256)
fused_write_kernel(const float* __restrict__ in,
                   float* __restrict__ out,
                   int B, int N, int K, int rows_per_thread,
                   int vec_ok) {
    int n_groups = (N + 7) >> 3;
    int g = blockIdx.x * blockDim.x + threadIdx.x;
    if (g >= n_groups) return;
    int n0 = g * 8;

    int b0 = blockIdx.y * rows_per_thread;
    int bend = b0 + rows_per_thread;
    if (bend > B) bend = B;

    if (vec_ok && n0 + 8 <= N) {
        int4 iv0 = *reinterpret_cast<const int4*>(&g_inv[n0]);
        int4 iv1 = *reinterpret_cast<const int4*>(&g_inv[n0 + 4]);
        bool anyhit = (iv0.x >= 0) | (iv0.y >= 0) | (iv0.z >= 0) | (iv0.w >= 0) |
                      (iv1.x >= 0) | (iv1.y >= 0) | (iv1.z >= 0) | (iv1.w >= 0);
        float4 z = make_float4(0.f, 0.f, 0.f, 0.f);
        if (!anyhit) {
            #pragma unroll 4
            for (int b = b0; b < bend; b++) {
                stcs256(out + (long long)b * N + n0, z, z);
            }
        } else {
            bool dup = (g_dup != 0);       // uniform; zero path never sees this
            for (int b = b0; b < bend; b++) {
                const float* rb = in + (long long)b * K;
                float4 v0 = gather4(rb, iv0, dup);
                float4 v1 = gather4(rb, iv1, dup);
                stcs256(out + (long long)b * N + n0, v0, v1);
            }
        }
    } else {
        // Scalar tail / unaligned fallback (duplicate-exact via chain).
        for (int c = n0; c < n0 + 8 && c < N; c++) {
            int j = g_inv[c];
            for (int b = b0; b < bend; b++) {
                const float* rb = in + (long long)b * K;
                float v = (j >= 0) ? chain_sum(rb, j) : 0.f;
                out[(long long)b * N + c] = v;
            }
        }
    }
}

// ---- Fallback path (shape outside map limits): fill + atomic scatter ----
__global__ void zero_fill_kernel(float4* __restrict__ out4, long long n4) {
    long long i = (long long)blockIdx.x * blockDim.x + threadIdx.x;
    long long stride = (long long)gridDim.x * blockDim.x;
    float4 z = make_float4(0.f, 0.f, 0.f, 0.f);
    for (; i < n4; i += stride) out4[i] = z;
}

__global__ void scatter_add_kernel(const float* __restrict__ in,
                                   const void* __restrict__ idx_raw,
                                   float* __restrict__ out,
                                   int B, int K, long long N) {
    long long t = (long long)blockIdx.x * blockDim.x + threadIdx.x;
    long long total = (long long)B * K;
    if (t >= total) return;
    int b = (int)(t / K);
    int j = (int)(t % K);
    bool is64 = detect_is64((const unsigned int*)idx_raw, K);
    long long col = load_idx(idx_raw, j, is64);
    atomicAdd(&out[(long long)b * N + col], in[(long long)b * K + j]);
}

extern "C" void kernel_launch(void* const* d_in, const int* in_sizes, int n_in,
                              void* d_out, int out_size) {
    const float* inputs = (const float*)d_in[0];
    const void* idx = d_in[1];
    float* out = (float*)d_out;

    int total_in = in_sizes[0];   // B * K
    int K = in_sizes[1];          // observed count
    int B = total_in / K;
    long long Nll = (long long)out_size / B;
    int N = (int)Nll;

    if (Nll <= INV_CAP && K <= MAX_K) {
        // Node 1: deterministic all-column build (no init, no fixup needed).
        int bblocks = (N + 255) / 256;
        build_all_kernel<<<bblocks, 256, K * (int)sizeof(int)>>>(idx, K, N);

        // Node 2: single fused streaming write of the whole output.
        const int ROWS = 8;
        int n_groups = (N + 7) / 8;
        // 32B alignment of every row's group start requires N % 8 == 0.
        int vec_ok = ((N & 7) == 0) ? 1 : 0;
        dim3 block(256, 1, 1);
        dim3 grid((n_groups + 255) / 256, (B + ROWS - 1) / ROWS, 1);
        fused_write_kernel<<<grid, block>>>(inputs, out, B, N, K, ROWS, vec_ok);
    } else {
        // Fallback: zero-fill + atomic scatter.
        long long n4 = (long long)out_size / 4;
        int threads = 256;
        long long blocks_ll = (n4 + threads - 1) / threads;
        int blocks = (blocks_ll > 0x7FFFFFF0LL) ? 0x7FFFFFF0 : (int)blocks_ll;
        zero_fill_kernel<<<blocks, threads>>>((float4*)out, n4);
        long long tail_start = n4 * 4;
        if (tail_start < (long long)out_size) {
            cudaMemsetAsync(out + tail_start, 0,
                            ((long long)out_size - tail_start) * sizeof(float), 0);
        }
        long long total = (long long)B * K;
        int sblocks = (int)((total + threads - 1) / threads);
        scatter_add_kernel<<<sblocks, threads>>>(inputs, idx, out, B, K, Nll);
    }
}